// round 16
// baseline (speedup 1.0000x reference)
#include <cuda_runtime.h>
#include <cuda_fp16.h>
#include <cstdint>

// ============================================================================
// T=1, h0=c0=0 => w_hh* unused, f-gate unused. Chain of small GEMMs on HMMA.
// R13: plain fp16 A and W, single MMA pass. R14: fp16x2 epilogue (tanh2).
// R15: fp16 MMA accumulators for LSTM layers (D arrives as fp16x2 h-pairs).
// R16: 64 rows/warp (4 m-tiles) -> weight LDS per row HALVED and 2x MMA ILP;
//      fc stores straight to gmem (fc staging + out read-back deleted);
//      A-buffer fp16-only (144B pitch, conflict-free);
//      atomic work-stealing over 64-row chunks (no static tail).
// Persistent: 148 CTAs x 512 thr; warps fully independent after weight copy.
// ============================================================================

#define NT    512
#define GRID  148
#define APH   144                    // fp16 A-row pitch (bank = 4g+q4, clean)
#define WIMG  42176                  // 40960 weights + 960 half biases + 256 fc
#define WARP_ABUF (64 * APH)         // 9216 B
#define SMEM_BYTES (WIMG + 16 * WARP_ABUF)   // 189632

// stage bases (bytes); per LSTM stage: [IG groups (KH*2048)][O frags (KH*1024)]
#define WB_L0 0
#define WB_L1 12288
#define WB_L2 18432
#define WB_L3 24576
#define WB_L4 30720
#define WB_FC 36864
#define BIAS_OFF 40960               // 480 halfs: [layer][i(32)|g(32)|o(32)]
#define FCB_OFF  41920               // 64 f32 fc biases

__device__ __align__(16) unsigned char g_img[WIMG];
__device__ unsigned g_ctr;

// ---------------- fast math ----------------
__device__ __forceinline__ uint32_t tanh2(uint32_t x) {
    uint32_t y; asm("tanh.approx.f16x2 %0, %1;" : "=r"(y) : "r"(x)); return y;
}
__device__ __forceinline__ uint32_t packh2(float a, float b) {
    __half2 v = __float22half2_rn(make_float2(a, b));
    return *reinterpret_cast<uint32_t*>(&v);
}
__device__ __forceinline__ __half2 as_h2(uint32_t v) {
    return *reinterpret_cast<__half2*>(&v);
}
__device__ __forceinline__ uint32_t as_u(__half2 v) {
    return *reinterpret_cast<uint32_t*>(&v);
}

// fused fp16x2 activation for an h-PAIR; C inputs already fp16x2.
__device__ __forceinline__ uint32_t act_h2(
    uint32_t ci2, uint32_t cg2, uint32_t co2,
    uint32_t bi2, uint32_t bg2, uint32_t bo2, __half2 H05)
{
    __half2 ui = __hfma2(as_h2(ci2), H05, as_h2(bi2));
    __half2 si = __hfma2(as_h2(tanh2(as_u(ui))), H05, H05);
    __half2 ug = __hadd2(as_h2(cg2), as_h2(bg2));
    __half2 c2 = __hmul2(si, as_h2(tanh2(as_u(ug))));
    uint32_t tc = tanh2(as_u(c2));
    __half2 uo = __hfma2(as_h2(co2), H05, as_h2(bo2));
    __half2 so = __hfma2(as_h2(tanh2(as_u(uo))), H05, H05);
    return as_u(__hmul2(so, as_h2(tc)));
}

// ---------------- mma ----------------
__device__ __forceinline__ void mma_f16h(uint32_t c[2],
    const uint32_t a[4], uint32_t b0, uint32_t b1) {
    asm volatile(
        "mma.sync.aligned.m16n8k16.row.col.f16.f16.f16.f16 "
        "{%0,%1},{%2,%3,%4,%5},{%6,%7},{%0,%1};"
        : "+r"(c[0]), "+r"(c[1])
        : "r"(a[0]), "r"(a[1]), "r"(a[2]), "r"(a[3]), "r"(b0), "r"(b1));
}
__device__ __forceinline__ void mma_f16(float c[4],
    const uint32_t a[4], uint32_t b0, uint32_t b1) {
    asm volatile(
        "mma.sync.aligned.m16n8k16.row.col.f32.f16.f16.f32 "
        "{%0,%1,%2,%3},{%4,%5,%6,%7},{%8,%9},{%0,%1,%2,%3};"
        : "+f"(c[0]), "+f"(c[1]), "+f"(c[2]), "+f"(c[3])
        : "r"(a[0]), "r"(a[1]), "r"(a[2]), "r"(a[3]), "r"(b0), "r"(b1));
}

// ---------------- reset (graph-replayed before main each launch) ----------
__global__ void _LSTM_reset() { g_ctr = 0u; }

// ---------------- weight pack: v2 layout, plain fp16 (unchanged) -----------
__global__ void _LSTM_pack(const float* __restrict__ w_ih0,
                           const float* __restrict__ w_ih_rest,
                           const float* __restrict__ b_ih,
                           const float* __restrict__ b_hh,
                           const float* __restrict__ fc_w,
                           const float* __restrict__ fc_b) {
    int i = blockIdx.x * blockDim.x + threadIdx.x;
    if (i < 20480) {
        int s, q;
        if (i < 6144)        { s = 0; q = i; }
        else if (i < 18432)  { s = 1 + (i - 6144) / 3072; q = (i - 6144) % 3072; }
        else                 { s = 5; q = i - 18432; }
        int fid = q >> 7, r = q & 127;
        int lane = r >> 2, reg = (r >> 1) & 1, half = r & 1;
        int n = lane >> 2;
        int kel = (lane & 3) * 2 + half + reg * 8;
        float w; unsigned dst;
        if (s < 5) {
            const int KH = (s == 0) ? 4 : 2;
            const unsigned base =
                (s == 0) ? 0u : (unsigned)(12288 + (s - 1) * 6144);
            int kidx = fid / 12, nt = fid % 12;
            int gate = nt >> 2, ntj = nt & 3;
            int k = kidx * 16 + kel;
            int j = gate * 32 + ntj * 8 + n;
            int rr = (j < 32) ? j : j + 32;
            if (s == 0) w = w_ih0[rr * 64 + k];
            else        w = w_ih_rest[(s - 1) * 4096 + rr * 32 + k];
            if (gate < 2)
                dst = base + (unsigned)(kidx * 4 + ntj) * 512
                    + lane * 16 + gate * 8 + reg * 4 + half * 2;
            else
                dst = base + (unsigned)KH * 2048 + (unsigned)(kidx * 4 + ntj) * 256
                    + lane * 8 + reg * 4 + half * 2;
            *(__half*)(g_img + dst) = __float2half_rn(w);
        } else {
            int kidx = fid / 8, nt = fid % 8;   // fid 0..15
            int k = kidx * 16 + kel;
            int j = nt * 8 + n;
            w = fc_w[j * 32 + k];
            dst = WB_FC + (unsigned)(kidx * 4 + (nt >> 1)) * 512
                + lane * 16 + (nt & 1) * 8 + reg * 4 + half * 2;
            *(__half*)(g_img + dst) = __float2half_rn(w);
        }
    } else if (i < 20480 + 480) {
        int b = i - 20480;                  // LSTM biases -> half
        int l = b / 96, j = b % 96;
        int rr = (j < 32) ? j : j + 32;
        float v = b_ih[l * 128 + rr] + b_hh[l * 128 + rr];
        if (j < 32 || j >= 64) v *= 0.5f;   // i,o rows: sig via tanh(x/2)
        *(__half*)(g_img + BIAS_OFF + b * 2) = __float2half_rn(v);
    } else if (i < 20480 + 480 + 64) {
        int b = i - 20480 - 480;            // fc biases -> f32
        *(float*)(g_img + FCB_OFF + b * 4) = fc_b[b];
    }
}

// -------- one 96-col LSTM layer: 4 m-tiles, A in regs, fp16 accum ----------
template<int KH>
__device__ __forceinline__ void layer96(
    const unsigned char* __restrict__ wimg, uint32_t wbase,
    const unsigned char* __restrict__ biasB, unsigned char* __restrict__ Abuf,
    int lane, __half2 H05)
{
    const int g = lane >> 2, q4 = lane & 3;
    uint32_t Ah[4][KH][4];
#pragma unroll
    for (int m = 0; m < 4; m++)
#pragma unroll
        for (int tk = 0; tk < KH; tk++) {
            const unsigned char* ab =
                Abuf + (m * 16 + g) * APH + 32 * tk + 4 * q4;
            Ah[m][tk][0] = *(const uint32_t*)ab;
            Ah[m][tk][1] = *(const uint32_t*)(ab + 8 * APH);
            Ah[m][tk][2] = *(const uint32_t*)(ab + 16);
            Ah[m][tk][3] = *(const uint32_t*)(ab + 8 * APH + 16);
        }
    __syncwarp();   // all lanes' A in regs before any h writes below

    const unsigned char* wIG = wimg + wbase + lane * 16;
    const unsigned char* wO  = wimg + wbase + KH * 2048 + lane * 8;

#pragma unroll
    for (int ntj = 0; ntj < 4; ntj++) {
        const unsigned char* aIG = wIG + ntj * 512;
        const unsigned char* aO  = wO  + ntj * 256;
        uint32_t Ci[4][2], Cg[4][2], Co[4][2];
#pragma unroll
        for (int m = 0; m < 4; m++) {
            Ci[m][0] = 0u; Ci[m][1] = 0u;
            Cg[m][0] = 0u; Cg[m][1] = 0u;
            Co[m][0] = 0u; Co[m][1] = 0u;
        }
#pragma unroll
        for (int t = 0; t < KH; t++) {
            uint4 igf = *(const uint4*)(aIG + t * 2048);
            uint2 of  = *(const uint2*)(aO  + t * 1024);
#pragma unroll
            for (int m = 0; m < 4; m++) {
                mma_f16h(Ci[m], Ah[m][t], igf.x, igf.y);
                mma_f16h(Cg[m], Ah[m][t], igf.z, igf.w);
                mma_f16h(Co[m], Ah[m][t], of.x,  of.y);
            }
        }
        const int col = ntj * 8 + q4 * 2;
        const uint32_t bi2 = *(const uint32_t*)(biasB + col * 2);
        const uint32_t bg2 = *(const uint32_t*)(biasB + 64 + col * 2);
        const uint32_t bo2 = *(const uint32_t*)(biasB + 128 + col * 2);
#pragma unroll
        for (int m = 0; m < 4; m++) {
            unsigned char* r0 =
                Abuf + (m * 16 + g) * APH + 4 * (ntj * 4 + q4);
            *(uint32_t*)r0 =
                act_h2(Ci[m][0], Cg[m][0], Co[m][0], bi2, bg2, bo2, H05);
            *(uint32_t*)(r0 + 8 * APH) =
                act_h2(Ci[m][1], Cg[m][1], Co[m][1], bi2, bg2, bo2, H05);
        }
    }
    __syncwarp();
}

// -------- fc: 4 m-tiles, A in regs, f32 accum, DIRECT gmem stores ----------
__device__ __forceinline__ void fc_stage(
    const unsigned char* __restrict__ wimg,
    const float* __restrict__ fb, const unsigned char* __restrict__ Abuf,
    int lane, float* __restrict__ out, long long rowbase, int B)
{
    const int g = lane >> 2, q4 = lane & 3;
    uint32_t Ah[4][2][4];
#pragma unroll
    for (int m = 0; m < 4; m++)
#pragma unroll
        for (int tk = 0; tk < 2; tk++) {
            const unsigned char* ab =
                Abuf + (m * 16 + g) * APH + 32 * tk + 4 * q4;
            Ah[m][tk][0] = *(const uint32_t*)ab;
            Ah[m][tk][1] = *(const uint32_t*)(ab + 8 * APH);
            Ah[m][tk][2] = *(const uint32_t*)(ab + 16);
            Ah[m][tk][3] = *(const uint32_t*)(ab + 8 * APH + 16);
        }
    __syncwarp();

    const unsigned char* wp = wimg + WB_FC + lane * 16;

#pragma unroll
    for (int np = 0; np < 4; np++) {           // ntj pairs (2np, 2np+1)
        float C0[4][4], C1[4][4];
#pragma unroll
        for (int m = 0; m < 4; m++)
#pragma unroll
            for (int q = 0; q < 4; q++) { C0[m][q] = 0.f; C1[m][q] = 0.f; }
#pragma unroll
        for (int t = 0; t < 2; t++) {
            uint4 bf = *(const uint4*)(wp + (uint32_t)(t * 4 + np) * 512);
#pragma unroll
            for (int m = 0; m < 4; m++) {
                mma_f16(C0[m], Ah[m][t], bf.x, bf.y);
                mma_f16(C1[m], Ah[m][t], bf.z, bf.w);
            }
        }
#pragma unroll
        for (int half = 0; half < 2; half++) {
            float (*C)[4] = half ? C1 : C0;
            const int col = (np * 2 + half) * 8 + q4 * 2;
            const float b0 = fb[col], b1 = fb[col + 1];
#pragma unroll
            for (int m = 0; m < 4; m++) {
                long long rA = rowbase + m * 16 + g;
                long long rB = rA + 8;
                if (rA < B)
                    *(float2*)(out + rA * 64 + col) =
                        make_float2(C[m][0] + b0, C[m][1] + b1);
                if (rB < B)
                    *(float2*)(out + rB * 64 + col) =
                        make_float2(C[m][2] + b0, C[m][3] + b1);
            }
        }
    }
}

// ---------------- main persistent kernel ----------------
__global__ void __launch_bounds__(NT, 1)
_LSTM_main(const float* __restrict__ x, float* __restrict__ out, int B) {
    extern __shared__ unsigned char smem[];
    const int tid = threadIdx.x;
    const int wid = tid >> 5;
    const int lane = tid & 31;

#pragma unroll 4
    for (int p = tid; p < WIMG / 16; p += NT)
        ((uint4*)smem)[p] = ((const uint4*)g_img)[p];
    __syncthreads();

    unsigned char* Abuf = smem + WIMG + wid * WARP_ABUF;
    const unsigned char* biasB = smem + BIAS_OFF;
    const float* fcb = (const float*)(smem + FCB_OFF);
    const float4* x4 = (const float4*)x;
    const __half2 H05 = __floats2half2_rn(0.5f, 0.5f);

    const unsigned nchunks = (unsigned)((B + 63) >> 6);

    for (;;) {
        unsigned chunk = 0u;
        if (lane == 0) chunk = atomicAdd(&g_ctr, 1u);
        chunk = __shfl_sync(0xFFFFFFFFu, chunk, 0);
        if (chunk >= nchunks) break;
        const long long rowbase = (long long)chunk * 64;

        // ---- stage 64 x-rows as fp16 (row = 128B data, 144B pitch) ----
#pragma unroll
        for (int i = 0; i < 32; i++) {
            int p = lane + i * 32;
            int r = p >> 4, c4 = p & 15;
            long long grow = rowbase + r;
            float4 v = (grow < B) ? x4[grow * 16 + c4]
                                  : make_float4(0.f, 0.f, 0.f, 0.f);
            uint32_t h0 = packh2(v.x, v.y), h1 = packh2(v.z, v.w);
            *(uint2*)(Abuf + r * APH + 8 * c4) = make_uint2(h0, h1);
        }
        __syncwarp();

        // ---- 5 LSTM layers (in-place, A in regs, fp16 accum) ----
        layer96<4>(smem, WB_L0, biasB,       Abuf, lane, H05);
        layer96<2>(smem, WB_L1, biasB + 192, Abuf, lane, H05);
        layer96<2>(smem, WB_L2, biasB + 384, Abuf, lane, H05);
        layer96<2>(smem, WB_L3, biasB + 576, Abuf, lane, H05);
        layer96<2>(smem, WB_L4, biasB + 768, Abuf, lane, H05);

        // ---- fc: direct gmem stores ----
        fc_stage(smem, fcb, Abuf, lane, out, rowbase, B);
        __syncwarp();
    }
}

// ---------------- launch ----------------
extern "C" void kernel_launch(void* const* d_in, const int* in_sizes, int n_in,
                              void* d_out, int out_size) {
    (void)n_in; (void)out_size;
    const float* x         = (const float*)d_in[0];
    const float* w_ih0     = (const float*)d_in[1];
    // d_in[2] = w_hh0      (unused: h0 == 0, T == 1)
    const float* w_ih_rest = (const float*)d_in[3];
    // d_in[4] = w_hh_rest  (unused)
    const float* b_ih      = (const float*)d_in[5];
    const float* b_hh      = (const float*)d_in[6];
    const float* fc_w      = (const float*)d_in[7];
    const float* fc_b      = (const float*)d_in[8];
    float* out = (float*)d_out;

    int B = in_sizes[0] / 64;

    _LSTM_reset<<<1, 1>>>();
    _LSTM_pack<<<(20480 + 544 + 255) / 256, 256>>>(
        w_ih0, w_ih_rest, b_ih, b_hh, fc_w, fc_b);

    cudaFuncSetAttribute(_LSTM_main,
                         cudaFuncAttributeMaxDynamicSharedMemorySize, SMEM_BYTES);
    int nchunks = (B + 63) / 64;
    int grid = (nchunks < GRID) ? nchunks : GRID;
    _LSTM_main<<<grid, NT, SMEM_BYTES>>>(x, out, B);
}